// round 1
// baseline (speedup 1.0000x reference)
#include <cuda_runtime.h>
#include <math.h>

// MDCT: B=8, T=2^20, F=2048, hop=1024, N=1024, n_frames = T/hop + 1 = 1025
// out[b,f,k] = Re( FFT_2048( x_frame * window * pre )[k] * post[k] ) * sqrt(2/N)

#define FLEN 2048
#define NBINS 1024

// Precomputed tables (built per launch by setup_kernel; no allocation allowed)
__device__ float2 g_winpre[FLEN];   // window[n] * exp(-i*pi*n/F)
__device__ float2 g_tw[NBINS];      // exp(-2*pi*i*j/2048), j in [0,1024)
__device__ float2 g_post[NBINS];    // sqrt(2/N) * exp(-i*pi*n0*(k+0.5)/N), n0=(N+1)/2

__device__ __forceinline__ float2 cmulf(float2 a, float2 b) {
    return make_float2(a.x * b.x - a.y * b.y, a.x * b.y + a.y * b.x);
}

__global__ void mdct_setup_kernel(const float* __restrict__ window) {
    int i = blockIdx.x * blockDim.x + threadIdx.x;
    if (i < FLEN) {
        double s, c;
        sincospi(-(double)i / 2048.0, &s, &c);   // exp(-i*pi*i/2048)
        float w = window[i];
        g_winpre[i] = make_float2(w * (float)c, w * (float)s);
    }
    if (i < NBINS) {
        double s, c;
        sincospi(-(double)i / 1024.0, &s, &c);   // exp(-2*pi*i*j/2048)
        g_tw[i] = make_float2((float)c, (float)s);

        double n0 = 512.5;  // (N+1)/2
        double ang = -n0 * ((double)i + 0.5) / 1024.0;  // units of pi
        sincospi(ang, &s, &c);
        double scale = sqrt(2.0 / 1024.0);
        g_post[i] = make_float2((float)(c * scale), (float)(s * scale));
    }
}

__global__ __launch_bounds__(256) void mdct_kernel(
    const float* __restrict__ x, float* __restrict__ out,
    int T, int n_frames)
{
    __shared__ float2 buf[2][FLEN];  // 32 KB ping-pong for Stockham FFT

    const int tid = threadIdx.x;
    const int f = blockIdx.x;
    const int b = blockIdx.y;

    // Frame f covers padded indices [f*1024, f*1024+2048); xp[i] = x[i-1024] in-range else 0
    const float* xb = x + (size_t)b * (size_t)T;
    const int start = f * 1024 - 1024;

    // Load + window + pre-twiddle -> natural order into buf[0]
    #pragma unroll
    for (int qq = 0; qq < 8; qq++) {
        int n = tid + 256 * qq;
        int g = start + n;
        float xv = (g >= 0 && g < T) ? xb[g] : 0.0f;
        float2 wp = g_winpre[n];
        buf[0][n] = make_float2(xv * wp.x, xv * wp.y);
    }
    __syncthreads();

    int cur = 0;

    // 5 radix-4 Stockham DIF stages: n = 2048,512,128,32,8 ; s = 1,4,16,64,256
    #pragma unroll
    for (int st = 0; st < 5; st++) {
        const int logs = 2 * st;
        const int s = 1 << logs;
        const int smask = s - 1;
        const float2* __restrict__ X = buf[cur];
        float2* __restrict__ Y = buf[cur ^ 1];

        #pragma unroll
        for (int it = 0; it < 2; it++) {
            int i = tid + 256 * it;              // i in [0, 512)
            float2 a = X[i];
            float2 bb = X[i + 512];
            float2 c = X[i + 1024];
            float2 d = X[i + 1536];

            int twbase = i & ~smask;             // = p * s  (< 512)
            float2 w1 = g_tw[twbase];
            float2 w2 = g_tw[2 * twbase];        // < 1024, in table
            float2 w3 = cmulf(w1, w2);

            float2 apc = make_float2(a.x + c.x, a.y + c.y);
            float2 amc = make_float2(a.x - c.x, a.y - c.y);
            float2 bpd = make_float2(bb.x + d.x, bb.y + d.y);
            float2 bmd = make_float2(bb.x - d.x, bb.y - d.y);
            float2 jb  = make_float2(-bmd.y, bmd.x);   // i * (b - d)

            int q = i & smask;
            int j = 4 * i - 3 * q;               // = q + s*4p

            Y[j]         = make_float2(apc.x + bpd.x, apc.y + bpd.y);
            Y[j + s]     = cmulf(make_float2(amc.x - jb.x, amc.y - jb.y), w1);
            Y[j + 2 * s] = cmulf(make_float2(apc.x - bpd.x, apc.y - bpd.y), w2);
            Y[j + 3 * s] = cmulf(make_float2(amc.x + jb.x, amc.y + jb.y), w3);
        }
        __syncthreads();
        cur ^= 1;
    }

    // Final radix-2 stage: n = 2, s = 1024 (twiddle = 1)
    {
        const float2* __restrict__ X = buf[cur];
        float2* __restrict__ Y = buf[cur ^ 1];
        #pragma unroll
        for (int it = 0; it < 4; it++) {
            int i = tid + 256 * it;              // i in [0, 1024)
            float2 a = X[i];
            float2 bb = X[i + 1024];
            Y[i]        = make_float2(a.x + bb.x, a.y + bb.y);
            Y[i + 1024] = make_float2(a.x - bb.x, a.y - bb.y);
        }
        __syncthreads();
        cur ^= 1;
    }

    // Post-twiddle + real part + scale, first N bins
    float* ob = out + ((size_t)b * (size_t)n_frames + (size_t)f) * (size_t)NBINS;
    #pragma unroll
    for (int it = 0; it < 4; it++) {
        int k = tid + 256 * it;
        float2 Xk = buf[cur][k];
        float2 p = g_post[k];
        ob[k] = Xk.x * p.x - Xk.y * p.y;
    }
}

extern "C" void kernel_launch(void* const* d_in, const int* in_sizes, int n_in,
                              void* d_out, int out_size) {
    const float* x = (const float*)d_in[0];
    const float* window = (const float*)d_in[1];
    float* out = (float*)d_out;

    const int B = 8;
    const int T = in_sizes[0] / B;        // 1<<20
    const int n_frames = T / 1024 + 1;    // 1025

    mdct_setup_kernel<<<8, 256>>>(window);

    dim3 grid(n_frames, B);
    mdct_kernel<<<grid, 256>>>(x, out, T, n_frames);
}

// round 2
// speedup vs baseline: 2.2383x; 2.2383x over previous
#include <cuda_runtime.h>
#include <math.h>

// Fast MDCT: B=8, T=2^20, F=2048, hop=1024, N=1024, n_frames=1025.
// out[b,f,k] = sqrt(2/N) * sum_n y[n] cos(pi/N (n+0.5+N/2)(k+0.5)),  y = x_frame*window
// Algorithm: fold 2048 -> 1024 real u (DCT-IV), pack 512 complex v, pre-twiddle,
// 512-pt FFT (3 radix-8 Stockham passes, register-resident), post-twiddle.

#define FLEN 2048
#define NBINS 1024
#define NF 512
#define PHYS(i) ((i) + ((i) >> 4))       // smem pad: +1 float2 per 16
#define GROUP_FLOATS 3136                 // 2048 (xs / bufB) + 1088 (bufA, 544 float2)
#define NGROUPS 4
#define SMEM_FLOATS (GROUP_FLOATS * NGROUPS)

// Precomputed tables (setup kernel, fp64 trig)
__device__ float2 g_tw5[NF];    // exp(-2*pi*i*j/512)
__device__ float4 g_foldE[NF];  // (cE0.re, cE0.im, cE1.re, cE1.im)   coeffs * a[n]
__device__ float4 g_foldO[NF];  // (cO0.re, cO0.im, cO1.re, cO1.im)   coeffs * (i*a[n])
__device__ float2 g_bT[NF];     // sqrt(2/N) * exp(-i*pi*(4r+1)/4096)

__device__ __forceinline__ float2 cmulf(float2 a, float2 b) {
    return make_float2(a.x * b.x - a.y * b.y, a.x * b.y + a.y * b.x);
}
__device__ __forceinline__ float2 caddf(float2 a, float2 b) { return make_float2(a.x + b.x, a.y + b.y); }
__device__ __forceinline__ float2 csubf(float2 a, float2 b) { return make_float2(a.x - b.x, a.y - b.y); }

__global__ void mdct_setup(const float* __restrict__ w) {
    int n = blockIdx.x * blockDim.x + threadIdx.x;
    if (n >= NF) return;
    double s, c;

    sincospi(-(double)n / 256.0, &s, &c);              // exp(-2*pi*i*n/512)
    g_tw5[n] = make_float2((float)c, (float)s);

    sincospi(-(double)(4 * n + 1) / 4096.0, &s, &c);   // b[r]
    double sc = sqrt(2.0 / 1024.0);
    g_bT[n] = make_float2((float)(c * sc), (float)(s * sc));

    sincospi(-(double)n / 1024.0, &s, &c);             // a[n] = exp(-i*pi*n/1024)
    float ax = (float)c, ay = (float)s;
    float iax = -ay, iay = ax;                         // i*a

    // fold coefficients (signed window values)
    float e0, e1, o0, o1;
    if (n < 256) {
        e0 = -w[1535 - 2 * n]; e1 = -w[1536 + 2 * n];
        o0 =  w[511 - 2 * n];  o1 = -w[512 + 2 * n];
    } else {
        e0 =  w[2 * n - 512];  e1 = -w[1535 - 2 * n];
        o0 = -w[512 + 2 * n];  o1 = -w[2559 - 2 * n];
    }
    g_foldE[n] = make_float4(e0 * ax,  e0 * ay,  e1 * ax,  e1 * ay);
    g_foldO[n] = make_float4(o0 * iax, o0 * iay, o1 * iax, o1 * iay);
}

// One radix-8 Stockham DIF stage: 64 threads, 1 butterfly each (512 = 8*8*8).
// Y[q + 8*pbase + t*S] = DFT8(a)[t] * exp(-2*pi*i*t*pbase/512),  i=l, q=i%S, pbase=i-q
template <int S>
__device__ __forceinline__ void fft8_stage(const float2* __restrict__ X,
                                           float2* __restrict__ Y, int l) {
    float2 a0 = X[PHYS(l)];
    float2 a1 = X[PHYS(l + 64)];
    float2 a2 = X[PHYS(l + 128)];
    float2 a3 = X[PHYS(l + 192)];
    float2 a4 = X[PHYS(l + 256)];
    float2 a5 = X[PHYS(l + 320)];
    float2 a6 = X[PHYS(l + 384)];
    float2 a7 = X[PHYS(l + 448)];

    float2 e0 = caddf(a0, a4), o0 = csubf(a0, a4);
    float2 e1 = caddf(a1, a5), o1 = csubf(a1, a5);
    float2 e2 = caddf(a2, a6), o2 = csubf(a2, a6);
    float2 e3 = caddf(a3, a7), o3 = csubf(a3, a7);

    const float C = 0.70710678118654752f;
    // o_u *= w8^u ; w8 = exp(-i*pi/4) = (C,-C), w8^2 = -i, w8^3 = (-C,-C)
    float2 p1 = make_float2(C * (o1.x + o1.y), C * (o1.y - o1.x));
    float2 p2 = make_float2(o2.y, -o2.x);
    float2 p3 = make_float2(C * (o3.y - o3.x), -C * (o3.x + o3.y));

    // DFT4 of evens
    float2 t0 = caddf(e0, e2), t1 = csubf(e0, e2);
    float2 t2 = caddf(e1, e3), t3 = csubf(e1, e3);
    float2 E0 = caddf(t0, t2);
    float2 E2 = csubf(t0, t2);
    float2 E1 = make_float2(t1.x + t3.y, t1.y - t3.x);   // t1 - i*t3
    float2 E3 = make_float2(t1.x - t3.y, t1.y + t3.x);   // t1 + i*t3

    // DFT4 of twiddled odds
    float2 s0 = caddf(o0, p2), s1 = csubf(o0, p2);
    float2 s2 = caddf(p1, p3), s3 = csubf(p1, p3);
    float2 O0 = caddf(s0, s2);
    float2 O2 = csubf(s0, s2);
    float2 O1 = make_float2(s1.x + s3.y, s1.y - s3.x);
    float2 O3 = make_float2(s1.x - s3.y, s1.y + s3.x);

    float2 A[8] = {E0, O0, E1, O1, E2, O2, E3, O3};

    int q = l & (S - 1);
    int pbase = l - q;
    int j = q + 8 * pbase;

    if (S < 64) {   // last stage has pbase==0: no twiddles
#pragma unroll
        for (int t = 1; t < 8; t++) A[t] = cmulf(A[t], g_tw5[t * pbase]);
    }
#pragma unroll
    for (int t = 0; t < 8; t++) Y[PHYS(j + t * S)] = A[t];
}

__global__ __launch_bounds__(64 * NGROUPS) void mdct_main(
    const float* __restrict__ x, float* __restrict__ out,
    int T, int n_frames)
{
    extern __shared__ float smem[];
    const int tid = threadIdx.x;
    const int g = tid >> 6;          // frame group within CTA
    const int l = tid & 63;          // lane within group

    float*  xs   = smem + g * GROUP_FLOATS;        // 2048 floats (raw frame)
    float2* bufB = (float2*)xs;                     // reuses xs region after fold
    float2* bufA = (float2*)(xs + 2048);            // 544 float2

    const int f = blockIdx.x * NGROUPS + g;
    const int b = blockIdx.y;
    const bool active = f < n_frames;

    const float* xb = x + (size_t)b * (size_t)T;
    const int start = f * 1024 - 1024;              // padded-frame origin in x

    // ---- load frame (zero-padded at edges), float4 vectorized ----
    if (active) {
#pragma unroll
        for (int k = 0; k < 8; k++) {
            int n4 = (l + 64 * k) * 4;
            int gg = start + n4;
            float4 v = make_float4(0.f, 0.f, 0.f, 0.f);
            if (gg >= 0 && gg < T) v = *(const float4*)(xb + gg);
            *(float4*)(xs + n4) = v;
        }
    }
    __syncthreads();

    // ---- fold + pack + pre-twiddle: v[n] -> bufA ----
#pragma unroll
    for (int j = 0; j < 8; j++) {
        int n = l + 64 * j;
        int iE0, iE1, iO0, iO1;
        if (n < 256) {
            iE0 = 1535 - 2 * n; iE1 = 1536 + 2 * n;
            iO0 = 511 - 2 * n;  iO1 = 512 + 2 * n;
        } else {
            iE0 = 2 * n - 512;  iE1 = 1535 - 2 * n;
            iO0 = 512 + 2 * n;  iO1 = 2559 - 2 * n;
        }
        float4 cE = g_foldE[n];
        float4 cO = g_foldO[n];
        float x0 = xs[iE0], x1 = xs[iE1], x2 = xs[iO0], x3 = xs[iO1];
        float2 v;
        v.x = x0 * cE.x + x1 * cE.z + x2 * cO.x + x3 * cO.z;
        v.y = x0 * cE.y + x1 * cE.w + x2 * cO.y + x3 * cO.w;
        bufA[PHYS(n)] = v;
    }
    __syncthreads();

    // ---- 512-pt FFT: 3 radix-8 Stockham stages ----
    fft8_stage<1>(bufA, bufB, l);
    __syncthreads();
    fft8_stage<8>(bufB, bufA, l);
    __syncthreads();
    fft8_stage<64>(bufA, bufB, l);
    __syncthreads();

    // ---- post-twiddle + de-interleave into natural k order (smem staging) ----
    float* stageF = (float*)bufA;    // 1088 floats >= 1024
#pragma unroll
    for (int j = 0; j < 8; j++) {
        int r = l + 64 * j;
        float2 Tr = bufB[PHYS(r)];
        float2 bb = g_bT[r];
        stageF[2 * r]        = Tr.x * bb.x - Tr.y * bb.y;    //  Re(T*b) -> out[2r]
        stageF[1023 - 2 * r] = -(Tr.x * bb.y + Tr.y * bb.x); // -Im(T*b) -> out[1023-2r]
    }
    __syncthreads();

    // ---- coalesced store ----
    if (active) {
        float* ob = out + ((size_t)b * (size_t)n_frames + (size_t)f) * (size_t)NBINS;
#pragma unroll
        for (int m = 0; m < 4; m++) {
            int idx = (l + 64 * m) * 4;
            *(float4*)(ob + idx) = *(const float4*)(stageF + idx);
        }
    }
}

extern "C" void kernel_launch(void* const* d_in, const int* in_sizes, int n_in,
                              void* d_out, int out_size) {
    const float* x = (const float*)d_in[0];
    const float* window = (const float*)d_in[1];
    float* out = (float*)d_out;

    const int B = 8;
    const int T = in_sizes[0] / B;        // 1<<20
    const int n_frames = T / 1024 + 1;    // 1025

    cudaFuncSetAttribute(mdct_main, cudaFuncAttributeMaxDynamicSharedMemorySize,
                         SMEM_FLOATS * (int)sizeof(float));

    mdct_setup<<<2, 256>>>(window);

    dim3 grid((n_frames + NGROUPS - 1) / NGROUPS, B);
    mdct_main<<<grid, 64 * NGROUPS, SMEM_FLOATS * sizeof(float)>>>(x, out, T, n_frames);
}

// round 3
// speedup vs baseline: 2.2849x; 1.0208x over previous
#include <cuda_runtime.h>
#include <math.h>

// Fast MDCT: B=8, T=2^20, F=2048, hop=1024, N=1024, n_frames=1025.
// out[b,f,k] = sqrt(2/N) * sum_n y[n] cos(pi/N (n+0.5+N/2)(k+0.5)),  y = x_frame*window
// Algorithm: fold 2048 -> 1024 real u (DCT-IV), pack 512 complex v, pre-twiddle,
// 512-pt FFT (3 radix-8 Stockham passes, register-resident), post-twiddle.

#define FLEN 2048
#define NBINS 1024
#define NF 512
#define PHYS(i) ((i) + ((i) >> 4))       // smem pad: +1 float2 per 16
#define GROUP_FLOATS 3136                 // 2048 (xs / bufB) + 1088 (bufA, 544 float2)
#define NGROUPS 4
#define SMEM_FLOATS (GROUP_FLOATS * NGROUPS)

// Precomputed tables (setup kernel, fp64 trig)
__device__ float2 g_tw5[NF];    // exp(-2*pi*i*j/512)
__device__ float4 g_foldE[NF];  // (cE0.re, cE0.im, cE1.re, cE1.im)   coeffs * a[n]
__device__ float4 g_foldO[NF];  // (cO0.re, cO0.im, cO1.re, cO1.im)   coeffs * (i*a[n])
__device__ float2 g_bT[NF];     // sqrt(2/N) * exp(-i*pi*(4r+1)/4096)

__device__ __forceinline__ float2 cmulf(float2 a, float2 b) {
    return make_float2(a.x * b.x - a.y * b.y, a.x * b.y + a.y * b.x);
}
__device__ __forceinline__ float2 caddf(float2 a, float2 b) { return make_float2(a.x + b.x, a.y + b.y); }
__device__ __forceinline__ float2 csubf(float2 a, float2 b) { return make_float2(a.x - b.x, a.y - b.y); }

__global__ void mdct_setup(const float* __restrict__ w) {
    int n = blockIdx.x * blockDim.x + threadIdx.x;
    if (n >= NF) return;
    double s, c;

    sincospi(-(double)n / 256.0, &s, &c);              // exp(-2*pi*i*n/512)
    g_tw5[n] = make_float2((float)c, (float)s);

    sincospi(-(double)(4 * n + 1) / 4096.0, &s, &c);   // b[r]
    double sc = sqrt(2.0 / 1024.0);
    g_bT[n] = make_float2((float)(c * sc), (float)(s * sc));

    sincospi(-(double)n / 1024.0, &s, &c);             // a[n] = exp(-i*pi*n/1024)
    float ax = (float)c, ay = (float)s;
    float iax = -ay, iay = ax;                         // i*a

    // fold coefficients (signed window values)
    float e0, e1, o0, o1;
    if (n < 256) {
        e0 = -w[1535 - 2 * n]; e1 = -w[1536 + 2 * n];
        o0 =  w[511 - 2 * n];  o1 = -w[512 + 2 * n];
    } else {
        e0 =  w[2 * n - 512];  e1 = -w[1535 - 2 * n];
        o0 = -w[512 + 2 * n];  o1 = -w[2559 - 2 * n];
    }
    g_foldE[n] = make_float4(e0 * ax,  e0 * ay,  e1 * ax,  e1 * ay);
    g_foldO[n] = make_float4(o0 * iax, o0 * iay, o1 * iax, o1 * iay);
}

// One radix-8 Stockham DIF stage: 64 threads, 1 butterfly each (512 = 8*8*8).
// Y[q + 8*pbase + t*S] = DFT8(a)[t] * exp(-2*pi*i*t*pbase/512),  i=l, q=i%S, pbase=i-q
template <int S>
__device__ __forceinline__ void fft8_stage(const float2* __restrict__ X,
                                           float2* __restrict__ Y, int l) {
    float2 a0 = X[PHYS(l)];
    float2 a1 = X[PHYS(l + 64)];
    float2 a2 = X[PHYS(l + 128)];
    float2 a3 = X[PHYS(l + 192)];
    float2 a4 = X[PHYS(l + 256)];
    float2 a5 = X[PHYS(l + 320)];
    float2 a6 = X[PHYS(l + 384)];
    float2 a7 = X[PHYS(l + 448)];

    float2 e0 = caddf(a0, a4), o0 = csubf(a0, a4);
    float2 e1 = caddf(a1, a5), o1 = csubf(a1, a5);
    float2 e2 = caddf(a2, a6), o2 = csubf(a2, a6);
    float2 e3 = caddf(a3, a7), o3 = csubf(a3, a7);

    const float C = 0.70710678118654752f;
    // o_u *= w8^u ; w8 = exp(-i*pi/4) = (C,-C), w8^2 = -i, w8^3 = (-C,-C)
    float2 p1 = make_float2(C * (o1.x + o1.y), C * (o1.y - o1.x));
    float2 p2 = make_float2(o2.y, -o2.x);
    float2 p3 = make_float2(C * (o3.y - o3.x), -C * (o3.x + o3.y));

    // DFT4 of evens
    float2 t0 = caddf(e0, e2), t1 = csubf(e0, e2);
    float2 t2 = caddf(e1, e3), t3 = csubf(e1, e3);
    float2 E0 = caddf(t0, t2);
    float2 E2 = csubf(t0, t2);
    float2 E1 = make_float2(t1.x + t3.y, t1.y - t3.x);   // t1 - i*t3
    float2 E3 = make_float2(t1.x - t3.y, t1.y + t3.x);   // t1 + i*t3

    // DFT4 of twiddled odds
    float2 s0 = caddf(o0, p2), s1 = csubf(o0, p2);
    float2 s2 = caddf(p1, p3), s3 = csubf(p1, p3);
    float2 O0 = caddf(s0, s2);
    float2 O2 = csubf(s0, s2);
    float2 O1 = make_float2(s1.x + s3.y, s1.y - s3.x);
    float2 O3 = make_float2(s1.x - s3.y, s1.y + s3.x);

    float2 A[8] = {E0, O0, E1, O1, E2, O2, E3, O3};

    int q = l & (S - 1);
    int pbase = l - q;
    int j = q + 8 * pbase;

    if (S < 64) {   // last stage has pbase==0: no twiddles
#pragma unroll
        for (int t = 1; t < 8; t++) A[t] = cmulf(A[t], g_tw5[t * pbase]);
    }
#pragma unroll
    for (int t = 0; t < 8; t++) Y[PHYS(j + t * S)] = A[t];
}

__global__ __launch_bounds__(64 * NGROUPS) void mdct_main(
    const float* __restrict__ x, float* __restrict__ out,
    int T, int n_frames)
{
    extern __shared__ float smem[];
    const int tid = threadIdx.x;
    const int g = tid >> 6;          // frame group within CTA
    const int l = tid & 63;          // lane within group

    float*  xs   = smem + g * GROUP_FLOATS;        // 2048 floats (raw frame)
    float2* bufB = (float2*)xs;                     // reuses xs region after fold
    float2* bufA = (float2*)(xs + 2048);            // 544 float2

    const int f = blockIdx.x * NGROUPS + g;
    const int b = blockIdx.y;
    const bool active = f < n_frames;

    const float* xb = x + (size_t)b * (size_t)T;
    const int start = f * 1024 - 1024;              // padded-frame origin in x

    // ---- load frame (zero-padded at edges), float4 vectorized ----
    if (active) {
#pragma unroll
        for (int k = 0; k < 8; k++) {
            int n4 = (l + 64 * k) * 4;
            int gg = start + n4;
            float4 v = make_float4(0.f, 0.f, 0.f, 0.f);
            if (gg >= 0 && gg < T) v = *(const float4*)(xb + gg);
            *(float4*)(xs + n4) = v;
        }
    }
    __syncthreads();

    // ---- fold + pack + pre-twiddle: v[n] -> bufA ----
#pragma unroll
    for (int j = 0; j < 8; j++) {
        int n = l + 64 * j;
        int iE0, iE1, iO0, iO1;
        if (n < 256) {
            iE0 = 1535 - 2 * n; iE1 = 1536 + 2 * n;
            iO0 = 511 - 2 * n;  iO1 = 512 + 2 * n;
        } else {
            iE0 = 2 * n - 512;  iE1 = 1535 - 2 * n;
            iO0 = 512 + 2 * n;  iO1 = 2559 - 2 * n;
        }
        float4 cE = g_foldE[n];
        float4 cO = g_foldO[n];
        float x0 = xs[iE0], x1 = xs[iE1], x2 = xs[iO0], x3 = xs[iO1];
        float2 v;
        v.x = x0 * cE.x + x1 * cE.z + x2 * cO.x + x3 * cO.z;
        v.y = x0 * cE.y + x1 * cE.w + x2 * cO.y + x3 * cO.w;
        bufA[PHYS(n)] = v;
    }
    __syncthreads();

    // ---- 512-pt FFT: 3 radix-8 Stockham stages ----
    fft8_stage<1>(bufA, bufB, l);
    __syncthreads();
    fft8_stage<8>(bufB, bufA, l);
    __syncthreads();
    fft8_stage<64>(bufA, bufB, l);
    __syncthreads();

    // ---- post-twiddle + de-interleave into natural k order (smem staging) ----
    float* stageF = (float*)bufA;    // 1088 floats >= 1024
#pragma unroll
    for (int j = 0; j < 8; j++) {
        int r = l + 64 * j;
        float2 Tr = bufB[PHYS(r)];
        float2 bb = g_bT[r];
        stageF[2 * r]        = Tr.x * bb.x - Tr.y * bb.y;    //  Re(T*b) -> out[2r]
        stageF[1023 - 2 * r] = -(Tr.x * bb.y + Tr.y * bb.x); // -Im(T*b) -> out[1023-2r]
    }
    __syncthreads();

    // ---- coalesced store ----
    if (active) {
        float* ob = out + ((size_t)b * (size_t)n_frames + (size_t)f) * (size_t)NBINS;
#pragma unroll
        for (int m = 0; m < 4; m++) {
            int idx = (l + 64 * m) * 4;
            *(float4*)(ob + idx) = *(const float4*)(stageF + idx);
        }
    }
}

extern "C" void kernel_launch(void* const* d_in, const int* in_sizes, int n_in,
                              void* d_out, int out_size) {
    const float* x = (const float*)d_in[0];
    const float* window = (const float*)d_in[1];
    float* out = (float*)d_out;

    const int B = 8;
    const int T = in_sizes[0] / B;        // 1<<20
    const int n_frames = T / 1024 + 1;    // 1025

    cudaFuncSetAttribute(mdct_main, cudaFuncAttributeMaxDynamicSharedMemorySize,
                         SMEM_FLOATS * (int)sizeof(float));

    mdct_setup<<<2, 256>>>(window);

    dim3 grid((n_frames + NGROUPS - 1) / NGROUPS, B);
    mdct_main<<<grid, 64 * NGROUPS, SMEM_FLOATS * sizeof(float)>>>(x, out, T, n_frames);
}

// round 4
// speedup vs baseline: 2.5334x; 1.1087x over previous
#include <cuda_runtime.h>
#include <math.h>

// Fast MDCT: B=8, T=2^20, F=2048, hop=1024, N=1024, n_frames=1025.
// fold 2048 real -> 1024 real (DCT-IV) -> 512-pt complex FFT (3 radix-8 Stockham
// stages; stage 1 fused with fold, stage 3 fused with post-twiddle) -> out.

#define NBINS 1024
#define NF 512
#define PHYS(i) ((i) + ((i) >> 4))     // float2 pad: +1 per 16
#define XP(i)   ((i) + ((i) >> 5))     // float  pad: +1 per 32
#define XS_FLOATS 2112                  // 2048 + 64 pad (also hosts bufB: 1084 fl)
#define BA_FLOATS 1088                  // bufA: 544 float2 (also hosts stageF: 1054 fl)
#define GROUP_FLOATS (XS_FLOATS + BA_FLOATS)   // 3200
#define NGROUPS 4
#define SMEM_FLOATS (GROUP_FLOATS * NGROUPS)

__device__ float2 g_tw5[NF];    // exp(-2*pi*i*j/512)
__device__ float4 g_foldE[NF];
__device__ float4 g_foldO[NF];
__device__ float2 g_bT[NF];     // sqrt(2/N)*exp(-i*pi*(4r+1)/4096)

__device__ __forceinline__ float2 cmulf(float2 a, float2 b) {
    return make_float2(a.x * b.x - a.y * b.y, a.x * b.y + a.y * b.x);
}
__device__ __forceinline__ float2 caddf(float2 a, float2 b) { return make_float2(a.x + b.x, a.y + b.y); }
__device__ __forceinline__ float2 csubf(float2 a, float2 b) { return make_float2(a.x - b.x, a.y - b.y); }

__global__ void mdct_setup(const float* __restrict__ w) {
    int n = blockIdx.x * blockDim.x + threadIdx.x;
    if (n >= NF) return;
    double s, c;

    sincospi(-(double)n / 256.0, &s, &c);
    g_tw5[n] = make_float2((float)c, (float)s);

    sincospi(-(double)(4 * n + 1) / 4096.0, &s, &c);
    double sc = sqrt(2.0 / 1024.0);
    g_bT[n] = make_float2((float)(c * sc), (float)(s * sc));

    sincospi(-(double)n / 1024.0, &s, &c);
    float ax = (float)c, ay = (float)s;
    float iax = -ay, iay = ax;

    float e0, e1, o0, o1;
    if (n < 256) {
        e0 = -w[1535 - 2 * n]; e1 = -w[1536 + 2 * n];
        o0 =  w[511 - 2 * n];  o1 = -w[512 + 2 * n];
    } else {
        e0 =  w[2 * n - 512];  e1 = -w[1535 - 2 * n];
        o0 = -w[512 + 2 * n];  o1 = -w[2559 - 2 * n];
    }
    g_foldE[n] = make_float4(e0 * ax,  e0 * ay,  e1 * ax,  e1 * ay);
    g_foldO[n] = make_float4(o0 * iax, o0 * iay, o1 * iax, o1 * iay);
}

// In-register 8-pt DFT (DIF): A[k] = DFT8(a)[k], natural order.
__device__ __forceinline__ void dft8(const float2 a[8], float2 A[8]) {
    float2 e0 = caddf(a[0], a[4]), o0 = csubf(a[0], a[4]);
    float2 e1 = caddf(a[1], a[5]), o1 = csubf(a[1], a[5]);
    float2 e2 = caddf(a[2], a[6]), o2 = csubf(a[2], a[6]);
    float2 e3 = caddf(a[3], a[7]), o3 = csubf(a[3], a[7]);

    const float C = 0.70710678118654752f;
    float2 p1 = make_float2(C * (o1.x + o1.y), C * (o1.y - o1.x));
    float2 p2 = make_float2(o2.y, -o2.x);
    float2 p3 = make_float2(C * (o3.y - o3.x), -C * (o3.x + o3.y));

    float2 t0 = caddf(e0, e2), t1 = csubf(e0, e2);
    float2 t2 = caddf(e1, e3), t3 = csubf(e1, e3);
    A[0] = caddf(t0, t2);
    A[4] = csubf(t0, t2);
    A[2] = make_float2(t1.x + t3.y, t1.y - t3.x);
    A[6] = make_float2(t1.x - t3.y, t1.y + t3.x);

    float2 s0 = caddf(o0, p2), s1 = csubf(o0, p2);
    float2 s2 = caddf(p1, p3), s3 = csubf(p1, p3);
    A[1] = caddf(s0, s2);
    A[5] = csubf(s0, s2);
    A[3] = make_float2(s1.x + s3.y, s1.y - s3.x);
    A[7] = make_float2(s1.x - s3.y, s1.y + s3.x);
}

__global__ __launch_bounds__(64 * NGROUPS) void mdct_main(
    const float* __restrict__ x, float* __restrict__ out,
    int T, int n_frames)
{
    extern __shared__ float smem[];
    const int tid = threadIdx.x;
    const int g = tid >> 6;
    const int l = tid & 63;

    float*  xs     = smem + g * GROUP_FLOATS;       // padded 2048 (XP)
    float2* bufB   = (float2*)xs;                    // reused after fold (PHYS)
    float2* bufA   = (float2*)(xs + XS_FLOATS);      // PHYS
    float*  stageF = (float*)bufA;                   // reused after stage2 (XP)

    const int f = blockIdx.x * NGROUPS + g;
    const int b = blockIdx.y;
    const bool active = f < n_frames;

    const float* xb = x + (size_t)b * (size_t)T;
    const int start = f * 1024 - 1024;

    #define GBAR() asm volatile("bar.sync %0, 64;" :: "r"(g + 1) : "memory")

    // ---- load frame into padded smem (float4 gmem loads, scalar smem stores) ----
    if (active) {
#pragma unroll
        for (int k = 0; k < 8; k++) {
            int i4 = 4 * (l + 64 * k);
            int gg = start + i4;
            float4 v = make_float4(0.f, 0.f, 0.f, 0.f);
            if (gg >= 0 && gg < T) v = *(const float4*)(xb + gg);
            int p = XP(i4);
            xs[p] = v.x; xs[p + 1] = v.y; xs[p + 2] = v.z; xs[p + 3] = v.w;
        }
    }
    GBAR();

    // ---- fold + pre-twiddle (registers) + stage 1 radix-8 (registers) ----
    {
        float2 v[8];
#pragma unroll
        for (int j = 0; j < 8; j++) {
            int n = l + 64 * j;
            int iE0, iE1, iO0, iO1;
            if (n < 256) {
                iE0 = 1535 - 2 * n; iE1 = 1536 + 2 * n;
                iO0 = 511 - 2 * n;  iO1 = 512 + 2 * n;
            } else {
                iE0 = 2 * n - 512;  iE1 = 1535 - 2 * n;
                iO0 = 512 + 2 * n;  iO1 = 2559 - 2 * n;
            }
            float4 cE = g_foldE[n];
            float4 cO = g_foldO[n];
            float x0 = xs[XP(iE0)], x1 = xs[XP(iE1)];
            float x2 = xs[XP(iO0)], x3 = xs[XP(iO1)];
            v[j].x = x0 * cE.x + x1 * cE.z + x2 * cO.x + x3 * cO.z;
            v[j].y = x0 * cE.y + x1 * cE.w + x2 * cO.y + x3 * cO.w;
        }
        float2 A[8];
        dft8(v, A);
#pragma unroll
        for (int t = 1; t < 8; t++) A[t] = cmulf(A[t], g_tw5[t * l]);
#pragma unroll
        for (int t = 0; t < 8; t++) bufA[PHYS(8 * l + t)] = A[t];
    }
    GBAR();

    // ---- stage 2 radix-8 ----
    {
        float2 a[8];
#pragma unroll
        for (int t = 0; t < 8; t++) a[t] = bufA[PHYS(l + 64 * t)];
        float2 A[8];
        dft8(a, A);
        int q = l & 7;
        int pbase = l - q;
#pragma unroll
        for (int t = 1; t < 8; t++) A[t] = cmulf(A[t], g_tw5[t * pbase]);
        int j = 8 * l - 7 * q;
#pragma unroll
        for (int t = 0; t < 8; t++) bufB[PHYS(j + 8 * t)] = A[t];
    }
    GBAR();

    // ---- stage 3 radix-8 (no twiddle) fused with post-twiddle + de-interleave ----
    {
        float2 a[8];
#pragma unroll
        for (int t = 0; t < 8; t++) a[t] = bufB[PHYS(l + 64 * t)];
        float2 A[8];
        dft8(a, A);
#pragma unroll
        for (int t = 0; t < 8; t++) {
            int r = l + 64 * t;
            float2 bb = g_bT[r];
            stageF[XP(2 * r)]        = A[t].x * bb.x - A[t].y * bb.y;
            stageF[XP(1023 - 2 * r)] = -(A[t].x * bb.y + A[t].y * bb.x);
        }
    }
    GBAR();

    // ---- coalesced float4 store ----
    if (active) {
        float* ob = out + ((size_t)b * (size_t)n_frames + (size_t)f) * (size_t)NBINS;
#pragma unroll
        for (int m = 0; m < 4; m++) {
            int idx = 4 * (l + 64 * m);
            int p = XP(idx);
            float4 o = make_float4(stageF[p], stageF[p + 1], stageF[p + 2], stageF[p + 3]);
            *(float4*)(ob + idx) = o;
        }
    }
    #undef GBAR
}

extern "C" void kernel_launch(void* const* d_in, const int* in_sizes, int n_in,
                              void* d_out, int out_size) {
    const float* x = (const float*)d_in[0];
    const float* window = (const float*)d_in[1];
    float* out = (float*)d_out;

    const int B = 8;
    const int T = in_sizes[0] / B;
    const int n_frames = T / 1024 + 1;

    cudaFuncSetAttribute(mdct_main, cudaFuncAttributeMaxDynamicSharedMemorySize,
                         SMEM_FLOATS * (int)sizeof(float));

    mdct_setup<<<2, 256>>>(window);

    dim3 grid((n_frames + NGROUPS - 1) / NGROUPS, B);
    mdct_main<<<grid, 64 * NGROUPS, SMEM_FLOATS * sizeof(float)>>>(x, out, T, n_frames);
}

// round 5
// speedup vs baseline: 4.1097x; 1.6222x over previous
#include <cuda_runtime.h>
#include <math.h>

// Fast MDCT: B=8, T=2^20, F=2048, hop=1024, N=1024, n_frames=1025.
// fold 2048 real -> 1024 real (DCT-IV) -> 512-pt complex FFT (3 radix-8 Stockham
// stages; stage 1 fused with fold, stage 3 fused with post-twiddle) -> out.
// All twiddles/window values computed on the fly with MUFU (no tables, no setup kernel).

#define NBINS 1024
#define PHYS(i) ((i) + ((i) >> 4))     // float2 pad: +1 per 16
#define XP(i)   ((i) + ((i) >> 5))     // float  pad: +1 per 32
#define BUF_F2 544                      // 512 float2 padded (PHYS(511)=542)
#define GROUP_F2 (2 * BUF_F2)           // bufA + bufB
#define NGROUPS 4
#define SMEM_BYTES (GROUP_F2 * NGROUPS * (int)sizeof(float2))

#define PI_F 3.14159265358979323846f
#define W_UNIT   (PI_F / 2048.0f)       // window angle unit
#define A_UNIT   (-PI_F / 1024.0f)      // pre-twiddle a[n]
#define TW_UNIT  (-PI_F / 256.0f)       // FFT twiddle: exp(-2pi i m/512) = m*TW_UNIT
#define POST_UNIT (-PI_F / 4096.0f)     // post: (4r+1)*POST_UNIT
#define SCALE 0.04419417382415922f      // sqrt(2/1024)

__device__ __forceinline__ float2 cmulf(float2 a, float2 b) {
    return make_float2(a.x * b.x - a.y * b.y, a.x * b.y + a.y * b.x);
}
__device__ __forceinline__ float2 caddf(float2 a, float2 b) { return make_float2(a.x + b.x, a.y + b.y); }
__device__ __forceinline__ float2 csubf(float2 a, float2 b) { return make_float2(a.x - b.x, a.y - b.y); }

// In-register 8-pt DFT (DIF), natural order output.
__device__ __forceinline__ void dft8(const float2 a[8], float2 A[8]) {
    float2 e0 = caddf(a[0], a[4]), o0 = csubf(a[0], a[4]);
    float2 e1 = caddf(a[1], a[5]), o1 = csubf(a[1], a[5]);
    float2 e2 = caddf(a[2], a[6]), o2 = csubf(a[2], a[6]);
    float2 e3 = caddf(a[3], a[7]), o3 = csubf(a[3], a[7]);

    const float C = 0.70710678118654752f;
    float2 p1 = make_float2(C * (o1.x + o1.y), C * (o1.y - o1.x));
    float2 p2 = make_float2(o2.y, -o2.x);
    float2 p3 = make_float2(C * (o3.y - o3.x), -C * (o3.x + o3.y));

    float2 t0 = caddf(e0, e2), t1 = csubf(e0, e2);
    float2 t2 = caddf(e1, e3), t3 = csubf(e1, e3);
    A[0] = caddf(t0, t2);
    A[4] = csubf(t0, t2);
    A[2] = make_float2(t1.x + t3.y, t1.y - t3.x);
    A[6] = make_float2(t1.x - t3.y, t1.y + t3.x);

    float2 s0 = caddf(o0, p2), s1 = csubf(o0, p2);
    float2 s2 = caddf(p1, p3), s3 = csubf(p1, p3);
    A[1] = caddf(s0, s2);
    A[5] = csubf(s0, s2);
    A[3] = make_float2(s1.x + s3.y, s1.y - s3.x);
    A[7] = make_float2(s1.x - s3.y, s1.y + s3.x);
}

__global__ __launch_bounds__(64 * NGROUPS) void mdct_main(
    const float* __restrict__ x, float* __restrict__ out,
    int T, int n_frames)
{
    extern __shared__ float2 smem2[];
    const int tid = threadIdx.x;
    const int g = tid >> 6;
    const int l = tid & 63;

    float2* bufA   = smem2 + g * GROUP_F2;
    float2* bufB   = bufA + BUF_F2;
    float*  stageF = (float*)bufA;                 // reused after stage 2

    const int f = blockIdx.x * NGROUPS + g;
    const int b = blockIdx.y;
    const bool active = f < n_frames;

    const float* xb = x + (size_t)b * (size_t)T;
    const int start = f * 1024 - 1024;             // padded-frame origin

    #define GBAR() asm volatile("bar.sync %0, 64;" :: "r"(g + 1) : "memory")

    // ---- fold (direct gmem reads) + pre-twiddle + stage-1 radix-8, all in regs ----
    {
        float2 v[8];
#pragma unroll
        for (int j = 0; j < 8; j++) {
            int n = l + 64 * j;
            int i0, i1, i2, i3;
            float s0, s1r, s2, s3;
            if (n < 256) {
                i0 = 1535 - 2 * n; i1 = 1536 + 2 * n;
                i2 = 511 - 2 * n;  i3 = 512 + 2 * n;
                s0 = -1.f; s1r = -1.f; s2 = 1.f; s3 = -1.f;
            } else {
                i0 = 2 * n - 512;  i1 = 1535 - 2 * n;
                i2 = 512 + 2 * n;  i3 = 2559 - 2 * n;
                s0 = 1.f; s1r = -1.f; s2 = -1.f; s3 = -1.f;
            }
            int g0 = start + i0, g1 = start + i1, g2 = start + i2, g3 = start + i3;
            float x0 = 0.f, x1 = 0.f, x2 = 0.f, x3 = 0.f;
            if ((unsigned)g0 < (unsigned)T) x0 = xb[g0];
            if ((unsigned)g1 < (unsigned)T) x1 = xb[g1];
            if ((unsigned)g2 < (unsigned)T) x2 = xb[g2];
            if ((unsigned)g3 < (unsigned)T) x3 = xb[g3];

            float w0 = __sinf(((float)i0 + 0.5f) * W_UNIT);
            float w1 = __sinf(((float)i1 + 0.5f) * W_UNIT);
            float w2 = __sinf(((float)i2 + 0.5f) * W_UNIT);
            float w3 = __sinf(((float)i3 + 0.5f) * W_UNIT);

            float E = s0 * w0 * x0 + s1r * w1 * x1;
            float O = s2 * w2 * x2 + s3 * w3 * x3;

            float sa, ca;
            __sincosf((float)n * A_UNIT, &sa, &ca);
            v[j].x = E * ca - O * sa;
            v[j].y = E * sa + O * ca;
        }
        float2 A[8];
        dft8(v, A);
        float base = (float)l * TW_UNIT;
#pragma unroll
        for (int t = 1; t < 8; t++) {
            float sw, cw;
            __sincosf((float)t * base, &sw, &cw);
            A[t] = cmulf(A[t], make_float2(cw, sw));
        }
#pragma unroll
        for (int t = 0; t < 8; t++) bufA[PHYS(8 * l + t)] = A[t];
    }
    GBAR();

    // ---- stage 2 radix-8 ----
    {
        float2 a[8];
#pragma unroll
        for (int t = 0; t < 8; t++) a[t] = bufA[PHYS(l + 64 * t)];
        float2 A[8];
        dft8(a, A);
        int q = l & 7;
        int pbase = l - q;
        float base = (float)pbase * TW_UNIT;
#pragma unroll
        for (int t = 1; t < 8; t++) {
            float sw, cw;
            __sincosf((float)t * base, &sw, &cw);
            A[t] = cmulf(A[t], make_float2(cw, sw));
        }
        int j = 8 * l - 7 * q;
#pragma unroll
        for (int t = 0; t < 8; t++) bufB[PHYS(j + 8 * t)] = A[t];
    }
    GBAR();

    // ---- stage 3 radix-8 (no twiddle) fused with post-twiddle + de-interleave ----
    {
        float2 a[8];
#pragma unroll
        for (int t = 0; t < 8; t++) a[t] = bufB[PHYS(l + 64 * t)];
        float2 A[8];
        dft8(a, A);
#pragma unroll
        for (int t = 0; t < 8; t++) {
            int r = l + 64 * t;
            float sb, cb;
            __sincosf((float)(4 * r + 1) * POST_UNIT, &sb, &cb);
            stageF[XP(2 * r)]        = SCALE * (A[t].x * cb - A[t].y * sb);
            stageF[XP(1023 - 2 * r)] = -SCALE * (A[t].x * sb + A[t].y * cb);
        }
    }
    GBAR();

    // ---- coalesced float4 store ----
    if (active) {
        float* ob = out + ((size_t)b * (size_t)n_frames + (size_t)f) * (size_t)NBINS;
#pragma unroll
        for (int m = 0; m < 4; m++) {
            int idx = 4 * (l + 64 * m);
            int p = XP(idx);
            float4 o = make_float4(stageF[p], stageF[p + 1], stageF[p + 2], stageF[p + 3]);
            *(float4*)(ob + idx) = o;
        }
    }
    #undef GBAR
}

extern "C" void kernel_launch(void* const* d_in, const int* in_sizes, int n_in,
                              void* d_out, int out_size) {
    const float* x = (const float*)d_in[0];
    float* out = (float*)d_out;

    const int B = 8;
    const int T = in_sizes[0] / B;        // 1<<20
    const int n_frames = T / 1024 + 1;    // 1025

    dim3 grid((n_frames + NGROUPS - 1) / NGROUPS, B);
    mdct_main<<<grid, 64 * NGROUPS, SMEM_BYTES>>>(x, out, T, n_frames);
}